// round 1
// baseline (speedup 1.0000x reference)
#include <cuda_runtime.h>

#define NN 10000
#define EE 400000
#define HH 128
#define PAD 132

typedef unsigned long long u64;

// ---------------- device scratch (no allocation allowed) ----------------
__device__ float g_h  [NN * HH];
__device__ float g_hn [NN * HH];
__device__ float g_agg[NN * HH];
__device__ float g_inv[NN];
__device__ int   g_cnt[NN];

// ---------------- packed f32x2 helpers (sm_103a) ----------------
__device__ __forceinline__ u64 pack2(float x, float y) {
    u64 r; asm("mov.b64 %0,{%1,%2};" : "=l"(r) : "f"(x), "f"(y)); return r;
}
__device__ __forceinline__ float2 unpack2(u64 v) {
    float2 r; asm("mov.b64 {%0,%1},%2;" : "=f"(r.x), "=f"(r.y) : "l"(v)); return r;
}
__device__ __forceinline__ void ffma2(u64 &c, u64 a, u64 b) {
    asm("fma.rn.f32x2 %0,%1,%2,%0;" : "+l"(c) : "l"(a), "l"(b));
}

// micro-kernel: A tile transposed As[kk][e] (stride PAD), B tile Bs[kk][j] (stride 128)
// thread (ty,tx) computes rows ty*8..+7, cols tx*8..+7, acc as 8x4 f32x2
__device__ __forceinline__ void mm_tile_At(const float* __restrict__ As,
                                           const float* __restrict__ Bs,
                                           int ty, int tx, u64 acc[8][4]) {
#pragma unroll 8
    for (int kk = 0; kk < 32; ++kk) {
        const float* ar = &As[kk * PAD + ty * 8];
        float4 a0 = *(const float4*)ar;
        float4 a1 = *(const float4*)(ar + 4);
        const float* br = &Bs[kk * 128 + tx * 8];
        float4 bq0 = *(const float4*)br;
        float4 bq1 = *(const float4*)(br + 4);
        u64 bb[4] = { pack2(bq0.x, bq0.y), pack2(bq0.z, bq0.w),
                      pack2(bq1.x, bq1.y), pack2(bq1.z, bq1.w) };
        float af[8] = { a0.x, a0.y, a0.z, a0.w, a1.x, a1.y, a1.z, a1.w };
#pragma unroll
        for (int i = 0; i < 8; ++i) {
            u64 aa = pack2(af[i], af[i]);
#pragma unroll
            for (int jp = 0; jp < 4; ++jp) ffma2(acc[i][jp], aa, bb[jp]);
        }
    }
}

// micro-kernel: A row-major Ts[e][k] (stride PAD), B tile Bs[kk][j]
__device__ __forceinline__ void mm_tile_Ar(const float* __restrict__ Ts,
                                           const float* __restrict__ Bs,
                                           int ty, int tx, int kbase, u64 acc[8][4]) {
#pragma unroll 4
    for (int kk = 0; kk < 32; ++kk) {
        int k = kbase + kk;
        const float* br = &Bs[kk * 128 + tx * 8];
        float4 bq0 = *(const float4*)br;
        float4 bq1 = *(const float4*)(br + 4);
        u64 bb[4] = { pack2(bq0.x, bq0.y), pack2(bq0.z, bq0.w),
                      pack2(bq1.x, bq1.y), pack2(bq1.z, bq1.w) };
#pragma unroll
        for (int i = 0; i < 8; ++i) {
            float a = Ts[(ty * 8 + i) * PAD + k];
            u64 aa = pack2(a, a);
#pragma unroll
            for (int jp = 0; jp < 4; ++jp) ffma2(acc[i][jp], aa, bb[jp]);
        }
    }
}

// ---------------- small kernels ----------------
__global__ void k_zero_cnt() {
    int i = blockIdx.x * blockDim.x + threadIdx.x;
    if (i < NN) g_cnt[i] = 0;
}
__global__ void k_count(const int* __restrict__ ei) {
    int e = blockIdx.x * blockDim.x + threadIdx.x;
    if (e < EE) atomicAdd(&g_cnt[ei[EE + e]], 1);
}
__global__ void k_inv() {
    int i = blockIdx.x * blockDim.x + threadIdx.x;
    if (i < NN) g_inv[i] = 1.0f / fmaxf((float)g_cnt[i], 1.0f);
}
__global__ void k_zero_agg() {
    int i = blockIdx.x * blockDim.x + threadIdx.x;
    if (i < NN * HH / 4) ((float4*)g_agg)[i] = make_float4(0.f, 0.f, 0.f, 0.f);
}

// encoder: one block per node, 128 threads
__global__ void k_enc(const float* __restrict__ x,
                      const float* __restrict__ w1, const float* __restrict__ b1,
                      const float* __restrict__ w2, const float* __restrict__ b2) {
    __shared__ float xr[8];
    __shared__ float t[128];
    int n = blockIdx.x, j = threadIdx.x;
    if (j < 6) xr[j] = x[n * 6 + j];
    __syncthreads();
    float s = b1[j];
#pragma unroll
    for (int k = 0; k < 6; ++k) s += xr[k] * w1[k * 128 + j];
    t[j] = fmaxf(s, 0.f);
    __syncthreads();
    float s2 = b2[j];
#pragma unroll 8
    for (int k = 0; k < 128; ++k) s2 += t[k] * w2[k * 128 + j];
    g_h[(size_t)n * 128 + j] = s2;
}

// decoder: one block per node
__global__ void k_dec(const float* __restrict__ w1, const float* __restrict__ b1,
                      const float* __restrict__ w2, const float* __restrict__ b2,
                      float* __restrict__ out) {
    __shared__ float hr[128];
    __shared__ float red[4];
    int n = blockIdx.x, j = threadIdx.x;
    hr[j] = g_h[(size_t)n * 128 + j];
    __syncthreads();
    float s = b1[j];
#pragma unroll 8
    for (int k = 0; k < 128; ++k) s += hr[k] * w1[k * 128 + j];
    float tv = fmaxf(s, 0.f) * w2[j];
#pragma unroll
    for (int o = 16; o > 0; o >>= 1) tv += __shfl_xor_sync(0xffffffffu, tv, o);
    if ((j & 31) == 0) red[j >> 5] = tv;
    __syncthreads();
    if (j == 0) out[n] = red[0] + red[1] + red[2] + red[3] + b2[0];
}

// ---------------- message MLP + scatter (the hot kernel) ----------------
// grid = E/128 = 3125 blocks, 256 threads.  smem = As[32][PAD] + Bs[32][128] + Ts[128][PAD]
#define SMEM_BIG ((32 * PAD + 32 * 128 + 128 * PAD) * 4)

__global__ __launch_bounds__(256, 2) void k_msg(
    const int* __restrict__ ei, const float* __restrict__ eattr,
    const float* __restrict__ W1, const float* __restrict__ B1,
    const float* __restrict__ W2, const float* __restrict__ B2, int flip) {
    const float* __restrict__ hin = flip ? g_hn : g_h;
    extern __shared__ float sm[];
    float* As = sm;                 // [32][PAD] transposed m_in chunk
    float* Bs = sm + 32 * PAD;      // [32][128]
    float* Ts = Bs + 32 * 128;      // [128][PAD] relu(GEMM1)

    int tid = threadIdx.x;
    int tx = tid & 15, ty = tid >> 4;
    int e0 = blockIdx.x * 128;

    u64 acc[8][4];
#pragma unroll
    for (int i = 0; i < 8; ++i)
#pragma unroll
        for (int jp = 0; jp < 4; ++jp) acc[i][jp] = 0ull;

    // GEMM1: K = 259 (h[tgt] | h[src] | edge_attr), 9 tiles of 32
    for (int kt = 0; kt < 9; ++kt) {
        int kbase = kt * 32;
        __syncthreads();
#pragma unroll
        for (int r = 0; r < 16; ++r) {
            int idx = r * 256 + tid;
            int e = idx >> 5, kk = idx & 31;
            int k = kbase + kk;
            int eg = e0 + e;
            float v;
            if (k < 128)       v = hin[(size_t)ei[EE + eg] * 128 + k];
            else if (k < 256)  v = hin[(size_t)ei[eg] * 128 + (k - 128)];
            else if (k < 259)  v = eattr[(size_t)eg * 3 + (k - 256)];
            else               v = 0.f;
            As[kk * PAD + e] = v;
        }
#pragma unroll
        for (int r = 0; r < 16; ++r) {
            int idx = r * 256 + tid;
            int kk = idx >> 7, j = idx & 127;
            int k = kbase + kk;
            Bs[kk * 128 + j] = (k < 259) ? W1[k * 128 + j] : 0.f;
        }
        __syncthreads();
        mm_tile_At(As, Bs, ty, tx, acc);
    }

    // epilogue1: relu(+bias) -> Ts[e][k2]
    {
        float4 bb0 = *(const float4*)&B1[tx * 8];
        float4 bb1 = *(const float4*)&B1[tx * 8 + 4];
        float bj[8] = { bb0.x, bb0.y, bb0.z, bb0.w, bb1.x, bb1.y, bb1.z, bb1.w };
        __syncthreads();
#pragma unroll
        for (int i = 0; i < 8; ++i) {
            int e = ty * 8 + i;
#pragma unroll
            for (int jp = 0; jp < 4; ++jp) {
                float2 c = unpack2(acc[i][jp]);
                c.x = fmaxf(c.x + bj[2 * jp], 0.f);
                c.y = fmaxf(c.y + bj[2 * jp + 1], 0.f);
                *(float2*)&Ts[e * PAD + tx * 8 + 2 * jp] = c;
            }
        }
        __syncthreads();
    }

    // GEMM2: K = 128, 4 tiles
    u64 acc2[8][4];
#pragma unroll
    for (int i = 0; i < 8; ++i)
#pragma unroll
        for (int jp = 0; jp < 4; ++jp) acc2[i][jp] = 0ull;

    for (int kt = 0; kt < 4; ++kt) {
        __syncthreads();
#pragma unroll
        for (int r = 0; r < 16; ++r) {
            int idx = r * 256 + tid;
            int kk = idx >> 7, j = idx & 127;
            Bs[kk * 128 + j] = W2[(kt * 32 + kk) * 128 + j];
        }
        __syncthreads();
        mm_tile_Ar(Ts, Bs, ty, tx, kt * 32, acc2);
    }

    // epilogue2: m = acc2 + b2, atomic scatter-add into g_agg[tgt]
    {
        float4 bb0 = *(const float4*)&B2[tx * 8];
        float4 bb1 = *(const float4*)&B2[tx * 8 + 4];
        float bj[8] = { bb0.x, bb0.y, bb0.z, bb0.w, bb1.x, bb1.y, bb1.z, bb1.w };
#pragma unroll
        for (int i = 0; i < 8; ++i) {
            int eg = e0 + ty * 8 + i;
            int t = ei[EE + eg];
            float* dst = &g_agg[(size_t)t * 128 + tx * 8];
#pragma unroll
            for (int jp = 0; jp < 4; ++jp) {
                float2 c = unpack2(acc2[i][jp]);
                atomicAdd(&dst[2 * jp],     c.x + bj[2 * jp]);
                atomicAdd(&dst[2 * jp + 1], c.y + bj[2 * jp + 1]);
            }
        }
    }
}

// ---------------- update MLP + residual + layernorm ----------------
// grid = ceil(N/128) = 79 blocks
__global__ __launch_bounds__(256, 2) void k_update(
    const float* __restrict__ W1, const float* __restrict__ B1,
    const float* __restrict__ W2, const float* __restrict__ B2,
    const float* __restrict__ lng, const float* __restrict__ lnb, int flip) {
    const float* __restrict__ hin  = flip ? g_hn : g_h;
    float* __restrict__ hout       = flip ? g_h  : g_hn;
    extern __shared__ float sm[];
    float* As = sm;
    float* Bs = sm + 32 * PAD;
    float* Ts = Bs + 32 * 128;

    int tid = threadIdx.x;
    int tx = tid & 15, ty = tid >> 4;
    int n0 = blockIdx.x * 128;

    u64 acc[8][4];
#pragma unroll
    for (int i = 0; i < 8; ++i)
#pragma unroll
        for (int jp = 0; jp < 4; ++jp) acc[i][jp] = 0ull;

    // GEMM1: K = 256 ([h | agg*inv]), 8 tiles
    for (int kt = 0; kt < 8; ++kt) {
        int kbase = kt * 32;
        __syncthreads();
#pragma unroll
        for (int r = 0; r < 16; ++r) {
            int idx = r * 256 + tid;
            int e = idx >> 5, kk = idx & 31;
            int k = kbase + kk;
            int n = n0 + e;
            float v = 0.f;
            if (n < NN) {
                if (k < 128) v = hin[(size_t)n * 128 + k];
                else         v = g_agg[(size_t)n * 128 + (k - 128)] * g_inv[n];
            }
            As[kk * PAD + e] = v;
        }
#pragma unroll
        for (int r = 0; r < 16; ++r) {
            int idx = r * 256 + tid;
            int kk = idx >> 7, j = idx & 127;
            Bs[kk * 128 + j] = W1[(kbase + kk) * 128 + j];
        }
        __syncthreads();
        mm_tile_At(As, Bs, ty, tx, acc);
    }

    // epilogue1: relu(+bias) -> Ts
    {
        float4 bb0 = *(const float4*)&B1[tx * 8];
        float4 bb1 = *(const float4*)&B1[tx * 8 + 4];
        float bj[8] = { bb0.x, bb0.y, bb0.z, bb0.w, bb1.x, bb1.y, bb1.z, bb1.w };
        __syncthreads();
#pragma unroll
        for (int i = 0; i < 8; ++i) {
            int e = ty * 8 + i;
#pragma unroll
            for (int jp = 0; jp < 4; ++jp) {
                float2 c = unpack2(acc[i][jp]);
                c.x = fmaxf(c.x + bj[2 * jp], 0.f);
                c.y = fmaxf(c.y + bj[2 * jp + 1], 0.f);
                *(float2*)&Ts[e * PAD + tx * 8 + 2 * jp] = c;
            }
        }
        __syncthreads();
    }

    // GEMM2: K = 128, 4 tiles
    u64 acc2[8][4];
#pragma unroll
    for (int i = 0; i < 8; ++i)
#pragma unroll
        for (int jp = 0; jp < 4; ++jp) acc2[i][jp] = 0ull;

    for (int kt = 0; kt < 4; ++kt) {
        __syncthreads();
#pragma unroll
        for (int r = 0; r < 16; ++r) {
            int idx = r * 256 + tid;
            int kk = idx >> 7, j = idx & 127;
            Bs[kk * 128 + j] = W2[(kt * 32 + kk) * 128 + j];
        }
        __syncthreads();
        mm_tile_Ar(Ts, Bs, ty, tx, kt * 32, acc2);
    }

    // epilogue2: r = u + b2 + h (residual) -> Ts (reuse)
    {
        float4 bb0 = *(const float4*)&B2[tx * 8];
        float4 bb1 = *(const float4*)&B2[tx * 8 + 4];
        float bj[8] = { bb0.x, bb0.y, bb0.z, bb0.w, bb1.x, bb1.y, bb1.z, bb1.w };
        __syncthreads();   // all GEMM2 reads of Ts done
#pragma unroll
        for (int i = 0; i < 8; ++i) {
            int e = ty * 8 + i;
            int n = n0 + e;
#pragma unroll
            for (int jp = 0; jp < 4; ++jp) {
                float2 c = unpack2(acc2[i][jp]);
                float h0 = 0.f, h1 = 0.f;
                if (n < NN) {
                    float2 hv = *(const float2*)&hin[(size_t)n * 128 + tx * 8 + 2 * jp];
                    h0 = hv.x; h1 = hv.y;
                }
                c.x += bj[2 * jp] + h0;
                c.y += bj[2 * jp + 1] + h1;
                *(float2*)&Ts[e * PAD + tx * 8 + 2 * jp] = c;
            }
        }
        __syncthreads();
    }

    // layernorm: 8 warps x 16 rows
    {
        int wid = tid >> 5, lane = tid & 31;
        for (int rr = 0; rr < 16; ++rr) {
            int e = wid * 16 + rr;
            int n = n0 + e;
            float v0 = Ts[e * PAD + lane];
            float v1 = Ts[e * PAD + lane + 32];
            float v2 = Ts[e * PAD + lane + 64];
            float v3 = Ts[e * PAD + lane + 96];
            float s = v0 + v1 + v2 + v3;
#pragma unroll
            for (int o = 16; o > 0; o >>= 1) s += __shfl_xor_sync(0xffffffffu, s, o);
            float mu = s * (1.0f / 128.0f);
            float d0 = v0 - mu, d1 = v1 - mu, d2 = v2 - mu, d3 = v3 - mu;
            float q = d0 * d0 + d1 * d1 + d2 * d2 + d3 * d3;
#pragma unroll
            for (int o = 16; o > 0; o >>= 1) q += __shfl_xor_sync(0xffffffffu, q, o);
            float rs = rsqrtf(q * (1.0f / 128.0f) + 1e-5f);
            if (n < NN) {
                size_t base = (size_t)n * 128;
                hout[base + lane]      = d0 * rs * lng[lane]      + lnb[lane];
                hout[base + lane + 32] = d1 * rs * lng[lane + 32] + lnb[lane + 32];
                hout[base + lane + 64] = d2 * rs * lng[lane + 64] + lnb[lane + 64];
                hout[base + lane + 96] = d3 * rs * lng[lane + 96] + lnb[lane + 96];
            }
        }
    }
}

// ---------------- launch ----------------
extern "C" void kernel_launch(void* const* d_in, const int* in_sizes, int n_in,
                              void* d_out, int out_size) {
    const float* x      = (const float*)d_in[0];
    const int*   ei     = (const int*)  d_in[1];   // [2,E] int32 (JAX x64 off)
    const float* eattr  = (const float*)d_in[2];
    const float* enc_w1 = (const float*)d_in[3];
    const float* enc_b1 = (const float*)d_in[4];
    const float* enc_w2 = (const float*)d_in[5];
    const float* enc_b2 = (const float*)d_in[6];
    const float* msg_w1 = (const float*)d_in[7];   // [4,259,128]
    const float* msg_b1 = (const float*)d_in[8];
    const float* msg_w2 = (const float*)d_in[9];   // [4,128,128]
    const float* msg_b2 = (const float*)d_in[10];
    const float* upd_w1 = (const float*)d_in[11];  // [4,256,128]
    const float* upd_b1 = (const float*)d_in[12];
    const float* upd_w2 = (const float*)d_in[13];  // [4,128,128]
    const float* upd_b2 = (const float*)d_in[14];
    const float* ln_g   = (const float*)d_in[15];
    const float* ln_b   = (const float*)d_in[16];
    const float* dec_w1 = (const float*)d_in[17];
    const float* dec_b1 = (const float*)d_in[18];
    const float* dec_w2 = (const float*)d_in[19];
    const float* dec_b2 = (const float*)d_in[20];
    float* out = (float*)d_out;

    cudaFuncSetAttribute(k_msg,    cudaFuncAttributeMaxDynamicSharedMemorySize, SMEM_BIG);
    cudaFuncSetAttribute(k_update, cudaFuncAttributeMaxDynamicSharedMemorySize, SMEM_BIG);

    k_zero_cnt<<<(NN + 255) / 256, 256>>>();
    k_count<<<(EE + 255) / 256, 256>>>(ei);
    k_inv<<<(NN + 255) / 256, 256>>>();
    k_enc<<<NN, 128>>>(x, enc_w1, enc_b1, enc_w2, enc_b2);

    for (int l = 0; l < 4; ++l) {
        int flip = l & 1;
        k_zero_agg<<<(NN * HH / 4 + 255) / 256, 256>>>();
        k_msg<<<EE / 128, 256, SMEM_BIG>>>(
            ei, eattr,
            msg_w1 + (size_t)l * 259 * 128, msg_b1 + (size_t)l * 128,
            msg_w2 + (size_t)l * 128 * 128, msg_b2 + (size_t)l * 128, flip);
        k_update<<<(NN + 127) / 128, 256, SMEM_BIG>>>(
            upd_w1 + (size_t)l * 256 * 128, upd_b1 + (size_t)l * 128,
            upd_w2 + (size_t)l * 128 * 128, upd_b2 + (size_t)l * 128,
            ln_g + (size_t)l * 128, ln_b + (size_t)l * 128, flip);
    }
    // after l=3 (flip=1) result is in g_h
    k_dec<<<NN, 128>>>(dec_w1, dec_b1, dec_w2, dec_b2, out);
}

// round 2
// speedup vs baseline: 3.1303x; 3.1303x over previous
#include <cuda_runtime.h>

#define NN 10000
#define EE 400000
#define HH 128
#define TPAD 132   // Ts row stride (floats)
#define APAD 36    // 32-wide A-tile row stride (floats)

typedef unsigned long long u64;

// ---------------- device scratch ----------------
__device__ float g_h  [NN * HH];
__device__ float g_hn [NN * HH];
__device__ float g_agg[NN * HH];
__device__ float g_P  [NN * HH];
__device__ float g_Q  [NN * HH];
__device__ float g_inv[NN];
__device__ int   g_cnt[NN];

// ---------------- packed f32x2 helpers (sm_103a) ----------------
__device__ __forceinline__ u64 pack2(float x, float y) {
    u64 r; asm("mov.b64 %0,{%1,%2};" : "=l"(r) : "f"(x), "f"(y)); return r;
}
__device__ __forceinline__ float2 unpack2(u64 v) {
    float2 r; asm("mov.b64 {%0,%1},%2;" : "=f"(r.x), "=f"(r.y) : "l"(v)); return r;
}
__device__ __forceinline__ void ffma2(u64 &c, u64 a, u64 b) {
    asm("fma.rn.f32x2 %0,%1,%2,%0;" : "+l"(c) : "l"(a), "l"(b));
}

// row-major 32-K-tile micro-kernel: A rows [arow0..arow0+8), stride lda,
// k window [kbase, kbase+32); B tile Bs[kk][j] (stride 128).
// thread computes 8 rows x 8 cols (cols tx*8..+8) into acc[8][4] f32x2.
__device__ __forceinline__ void mm_row(const float* __restrict__ A, int lda,
                                       int arow0, int kbase,
                                       const float* __restrict__ Bs,
                                       int tx, u64 acc[8][4]) {
#pragma unroll
    for (int kq = 0; kq < 8; ++kq) {
        int k0 = kq * 4;
        u64 bb[4][4];
#pragma unroll
        for (int kk = 0; kk < 4; ++kk) {
            const float* br = &Bs[(k0 + kk) * 128 + tx * 8];
            float4 b0 = *(const float4*)br;
            float4 b1 = *(const float4*)(br + 4);
            bb[kk][0] = pack2(b0.x, b0.y); bb[kk][1] = pack2(b0.z, b0.w);
            bb[kk][2] = pack2(b1.x, b1.y); bb[kk][3] = pack2(b1.z, b1.w);
        }
#pragma unroll
        for (int i = 0; i < 8; ++i) {
            float4 av = *(const float4*)&A[(arow0 + i) * lda + kbase + k0];
            float af[4] = { av.x, av.y, av.z, av.w };
#pragma unroll
            for (int kk = 0; kk < 4; ++kk) {
                u64 aa = pack2(af[kk], af[kk]);
#pragma unroll
                for (int jp = 0; jp < 4; ++jp) ffma2(acc[i][jp], aa, bb[kk][jp]);
            }
        }
    }
}

__device__ __forceinline__ void red4(float* p, float a, float b, float c, float d) {
    asm volatile("red.global.add.v4.f32 [%0], {%1, %2, %3, %4};"
                 :: "l"(p), "f"(a), "f"(b), "f"(c), "f"(d) : "memory");
}

// ---------------- small kernels ----------------
__global__ void k_zero_cnt() {
    int i = blockIdx.x * blockDim.x + threadIdx.x;
    if (i < NN) g_cnt[i] = 0;
}
__global__ void k_count(const int* __restrict__ ei) {
    int e = blockIdx.x * blockDim.x + threadIdx.x;
    if (e < EE) atomicAdd(&g_cnt[ei[EE + e]], 1);
}
__global__ void k_inv() {
    int i = blockIdx.x * blockDim.x + threadIdx.x;
    if (i < NN) g_inv[i] = 1.0f / fmaxf((float)g_cnt[i], 1.0f);
}
__global__ void k_zero_agg() {
    int i = blockIdx.x * blockDim.x + threadIdx.x;
    if (i < NN * HH / 4) ((float4*)g_agg)[i] = make_float4(0.f, 0.f, 0.f, 0.f);
}

// encoder: one block per node, 128 threads
__global__ void k_enc(const float* __restrict__ x,
                      const float* __restrict__ w1, const float* __restrict__ b1,
                      const float* __restrict__ w2, const float* __restrict__ b2) {
    __shared__ float xr[8];
    __shared__ float t[128];
    int n = blockIdx.x, j = threadIdx.x;
    if (j < 6) xr[j] = x[n * 6 + j];
    __syncthreads();
    float s = b1[j];
#pragma unroll
    for (int k = 0; k < 6; ++k) s += xr[k] * w1[k * 128 + j];
    t[j] = fmaxf(s, 0.f);
    __syncthreads();
    float s2 = b2[j];
#pragma unroll 8
    for (int k = 0; k < 128; ++k) s2 += t[k] * w2[k * 128 + j];
    g_h[(size_t)n * 128 + j] = s2;
}

// decoder: one block per node
__global__ void k_dec(const float* __restrict__ w1, const float* __restrict__ b1,
                      const float* __restrict__ w2, const float* __restrict__ b2,
                      float* __restrict__ out) {
    __shared__ float hr[128];
    __shared__ float red[4];
    int n = blockIdx.x, j = threadIdx.x;
    hr[j] = g_h[(size_t)n * 128 + j];
    __syncthreads();
    float s = b1[j];
#pragma unroll 8
    for (int k = 0; k < 128; ++k) s += hr[k] * w1[k * 128 + j];
    float tv = fmaxf(s, 0.f) * w2[j];
#pragma unroll
    for (int o = 16; o > 0; o >>= 1) tv += __shfl_xor_sync(0xffffffffu, tv, o);
    if ((j & 31) == 0) red[j >> 5] = tv;
    __syncthreads();
    if (j == 0) out[n] = red[0] + red[1] + red[2] + red[3] + b2[0];
}

// ---------------- P/Q precompute: P = h@W1[0:128], Q = h@W1[128:256] ----------------
// grid (79, 2), 256 threads. smem: As[128][APAD] + Bs[32][128]
#define SM_PQ ((128 * APAD + 32 * 128) * 4)
__global__ __launch_bounds__(256, 2) void k_pq(const float* __restrict__ W1, int flip) {
    const float* __restrict__ hin = flip ? g_hn : g_h;
    extern __shared__ float sm[];
    float* As = sm;
    float* Bs = sm + 128 * APAD;
    int tid = threadIdx.x;
    int tx = tid & 15, ty = tid >> 4;
    int n0 = blockIdx.x * 128;
    int yoff = blockIdx.y * 128;      // 0 -> P (tgt half), 128 -> Q (src half)

    u64 acc[8][4];
#pragma unroll
    for (int i = 0; i < 8; ++i)
#pragma unroll
        for (int jp = 0; jp < 4; ++jp) acc[i][jp] = 0ull;

    for (int kt = 0; kt < 4; ++kt) {
        int kb = kt * 32;
        __syncthreads();
        // A tile: rows = nodes, cols = 32 k's, coalesced float4
#pragma unroll
        for (int r = 0; r < 4; ++r) {
            int idx = r * 256 + tid;           // 0..1023 float4 slots
            int e = idx >> 3, c4 = idx & 7;
            int n = n0 + e;
            float4 v = make_float4(0.f, 0.f, 0.f, 0.f);
            if (n < NN) v = *(const float4*)&hin[(size_t)n * 128 + kb + c4 * 4];
            *(float4*)&As[e * APAD + c4 * 4] = v;
        }
        // B tile
#pragma unroll
        for (int r = 0; r < 16; ++r) {
            int idx = r * 256 + tid;
            int kk = idx >> 7, j = idx & 127;
            Bs[kk * 128 + j] = W1[(size_t)(yoff + kb + kk) * 128 + j];
        }
        __syncthreads();
        mm_row(As, APAD, ty * 8, 0, Bs, tx, acc);
    }

    float* outp = blockIdx.y ? g_Q : g_P;
#pragma unroll
    for (int i = 0; i < 8; ++i) {
        int n = n0 + ty * 8 + i;
        if (n < NN) {
#pragma unroll
            for (int jp = 0; jp < 4; ++jp) {
                float2 c = unpack2(acc[i][jp]);
                *(float2*)&outp[(size_t)n * 128 + tx * 8 + 2 * jp] = c;
            }
        }
    }
}

// ---------------- edge kernel: T = relu(P[tgt]+Q[src]+ea@W1c+b1); m = T@W2+b2; scatter ----------------
// grid = E/128 = 3125, 256 threads. smem: Ts[128][TPAD] + Bs[32][128]
#define SM_EDGE ((128 * TPAD + 32 * 128) * 4)
__global__ __launch_bounds__(256, 2) void k_edge(
    const int* __restrict__ ei, const float* __restrict__ eattr,
    const float* __restrict__ W1, const float* __restrict__ B1,
    const float* __restrict__ W2, const float* __restrict__ B2) {
    extern __shared__ float sm[];
    float* Ts = sm;                    // [128][TPAD]
    float* Bs = sm + 128 * TPAD;       // [32][128]
    __shared__ int s_tg[128], s_sr[128];
    __shared__ float s_ea[128 * 3];
    __shared__ float s_w1c[3 * 128];
    __shared__ float s_b1[128];

    int tid = threadIdx.x;
    int tx = tid & 15, ty = tid >> 4;
    int e0 = blockIdx.x * 128;

    if (tid < 128) {
        s_tg[tid] = ei[EE + e0 + tid];
        s_sr[tid] = ei[e0 + tid];
        s_b1[tid] = B1[tid];
        s_w1c[tid]       = W1[(size_t)256 * 128 + tid];
        s_w1c[128 + tid] = W1[(size_t)257 * 128 + tid];
        s_w1c[256 + tid] = W1[(size_t)258 * 128 + tid];
    }
    for (int idx = tid; idx < 384; idx += 256) s_ea[idx] = eattr[(size_t)e0 * 3 + idx];
    __syncthreads();

    // build T rows: coalesced P/Q row gathers
#pragma unroll 4
    for (int r = 0; r < 16; ++r) {
        int idx = r * 256 + tid;          // 0..4095 float4 slots
        int e = idx >> 5, c4 = idx & 31;
        int tg = s_tg[e], sr = s_sr[e];
        float4 p = *(const float4*)&g_P[(size_t)tg * 128 + c4 * 4];
        float4 q = *(const float4*)&g_Q[(size_t)sr * 128 + c4 * 4];
        float ea0 = s_ea[e * 3], ea1 = s_ea[e * 3 + 1], ea2 = s_ea[e * 3 + 2];
        float4 w0 = *(const float4*)&s_w1c[c4 * 4];
        float4 w1v = *(const float4*)&s_w1c[128 + c4 * 4];
        float4 w2v = *(const float4*)&s_w1c[256 + c4 * 4];
        float4 bb = *(const float4*)&s_b1[c4 * 4];
        float4 t;
        t.x = fmaxf(p.x + q.x + ea0 * w0.x + ea1 * w1v.x + ea2 * w2v.x + bb.x, 0.f);
        t.y = fmaxf(p.y + q.y + ea0 * w0.y + ea1 * w1v.y + ea2 * w2v.y + bb.y, 0.f);
        t.z = fmaxf(p.z + q.z + ea0 * w0.z + ea1 * w1v.z + ea2 * w2v.z + bb.z, 0.f);
        t.w = fmaxf(p.w + q.w + ea0 * w0.w + ea1 * w1v.w + ea2 * w2v.w + bb.w, 0.f);
        *(float4*)&Ts[e * TPAD + c4 * 4] = t;
    }

    // GEMM2: K = 128, 4 tiles
    u64 acc[8][4];
#pragma unroll
    for (int i = 0; i < 8; ++i)
#pragma unroll
        for (int jp = 0; jp < 4; ++jp) acc[i][jp] = 0ull;

    for (int kt = 0; kt < 4; ++kt) {
        __syncthreads();
#pragma unroll
        for (int r = 0; r < 16; ++r) {
            int idx = r * 256 + tid;
            int kk = idx >> 7, j = idx & 127;
            Bs[kk * 128 + j] = W2[(size_t)(kt * 32 + kk) * 128 + j];
        }
        __syncthreads();
        mm_row(Ts, TPAD, ty * 8, kt * 32, Bs, tx, acc);
    }

    // epilogue: +b2, vector red scatter into g_agg[tgt]
    float4 b20 = *(const float4*)&B2[tx * 8];
    float4 b21 = *(const float4*)&B2[tx * 8 + 4];
#pragma unroll
    for (int i = 0; i < 8; ++i) {
        int t = s_tg[ty * 8 + i];
        float* dst = &g_agg[(size_t)t * 128 + tx * 8];
        float2 c0 = unpack2(acc[i][0]);
        float2 c1 = unpack2(acc[i][1]);
        float2 c2 = unpack2(acc[i][2]);
        float2 c3 = unpack2(acc[i][3]);
        red4(dst,     c0.x + b20.x, c0.y + b20.y, c1.x + b20.z, c1.y + b20.w);
        red4(dst + 4, c2.x + b21.x, c2.y + b21.y, c3.x + b21.z, c3.y + b21.w);
    }
}

// ---------------- update MLP + residual + layernorm ----------------
// grid = 79, 256 threads. smem: As[128][APAD] + Bs[32][128] + Ts[128][TPAD]
#define SM_UPD ((128 * APAD + 32 * 128 + 128 * TPAD) * 4)
__global__ __launch_bounds__(256, 2) void k_update(
    const float* __restrict__ W1, const float* __restrict__ B1,
    const float* __restrict__ W2, const float* __restrict__ B2,
    const float* __restrict__ lng, const float* __restrict__ lnb, int flip) {
    const float* __restrict__ hin  = flip ? g_hn : g_h;
    float* __restrict__ hout       = flip ? g_h  : g_hn;
    extern __shared__ float sm[];
    float* As = sm;                        // [128][APAD]
    float* Bs = sm + 128 * APAD;           // [32][128]
    float* Ts = Bs + 32 * 128;             // [128][TPAD]
    __shared__ float s_inv[128];

    int tid = threadIdx.x;
    int tx = tid & 15, ty = tid >> 4;
    int n0 = blockIdx.x * 128;

    if (tid < 128) {
        int n = n0 + tid;
        s_inv[tid] = (n < NN) ? g_inv[n] : 0.f;
    }

    u64 acc[8][4];
#pragma unroll
    for (int i = 0; i < 8; ++i)
#pragma unroll
        for (int jp = 0; jp < 4; ++jp) acc[i][jp] = 0ull;

    // GEMM1: K = 256 ([h | agg*inv]), 8 tiles
    for (int kt = 0; kt < 8; ++kt) {
        int kb = kt * 32;
        __syncthreads();
#pragma unroll
        for (int r = 0; r < 4; ++r) {
            int idx = r * 256 + tid;
            int e = idx >> 3, c4 = idx & 7;
            int n = n0 + e;
            float4 v = make_float4(0.f, 0.f, 0.f, 0.f);
            if (n < NN) {
                if (kb < 128) {
                    v = *(const float4*)&hin[(size_t)n * 128 + kb + c4 * 4];
                } else {
                    v = *(const float4*)&g_agg[(size_t)n * 128 + (kb - 128) + c4 * 4];
                    float iv = s_inv[e];
                    v.x *= iv; v.y *= iv; v.z *= iv; v.w *= iv;
                }
            }
            *(float4*)&As[e * APAD + c4 * 4] = v;
        }
#pragma unroll
        for (int r = 0; r < 16; ++r) {
            int idx = r * 256 + tid;
            int kk = idx >> 7, j = idx & 127;
            Bs[kk * 128 + j] = W1[(size_t)(kb + kk) * 128 + j];
        }
        __syncthreads();
        mm_row(As, APAD, ty * 8, 0, Bs, tx, acc);
    }

    // epilogue1: relu(+bias) -> Ts
    {
        float4 bb0 = *(const float4*)&B1[tx * 8];
        float4 bb1 = *(const float4*)&B1[tx * 8 + 4];
        float bj[8] = { bb0.x, bb0.y, bb0.z, bb0.w, bb1.x, bb1.y, bb1.z, bb1.w };
        __syncthreads();
#pragma unroll
        for (int i = 0; i < 8; ++i) {
            int e = ty * 8 + i;
#pragma unroll
            for (int jp = 0; jp < 4; ++jp) {
                float2 c = unpack2(acc[i][jp]);
                c.x = fmaxf(c.x + bj[2 * jp], 0.f);
                c.y = fmaxf(c.y + bj[2 * jp + 1], 0.f);
                *(float2*)&Ts[e * TPAD + tx * 8 + 2 * jp] = c;
            }
        }
        __syncthreads();
    }

    // GEMM2: K = 128, 4 tiles
    u64 acc2[8][4];
#pragma unroll
    for (int i = 0; i < 8; ++i)
#pragma unroll
        for (int jp = 0; jp < 4; ++jp) acc2[i][jp] = 0ull;

    for (int kt = 0; kt < 4; ++kt) {
        __syncthreads();
#pragma unroll
        for (int r = 0; r < 16; ++r) {
            int idx = r * 256 + tid;
            int kk = idx >> 7, j = idx & 127;
            Bs[kk * 128 + j] = W2[(size_t)(kt * 32 + kk) * 128 + j];
        }
        __syncthreads();
        mm_row(Ts, TPAD, ty * 8, kt * 32, Bs, tx, acc2);
    }

    // epilogue2: r = u + b2 + h -> Ts
    {
        float4 bb0 = *(const float4*)&B2[tx * 8];
        float4 bb1 = *(const float4*)&B2[tx * 8 + 4];
        float bj[8] = { bb0.x, bb0.y, bb0.z, bb0.w, bb1.x, bb1.y, bb1.z, bb1.w };
        __syncthreads();
#pragma unroll
        for (int i = 0; i < 8; ++i) {
            int e = ty * 8 + i;
            int n = n0 + e;
#pragma unroll
            for (int jp = 0; jp < 4; ++jp) {
                float2 c = unpack2(acc2[i][jp]);
                float h0 = 0.f, h1 = 0.f;
                if (n < NN) {
                    float2 hv = *(const float2*)&hin[(size_t)n * 128 + tx * 8 + 2 * jp];
                    h0 = hv.x; h1 = hv.y;
                }
                c.x += bj[2 * jp] + h0;
                c.y += bj[2 * jp + 1] + h1;
                *(float2*)&Ts[e * TPAD + tx * 8 + 2 * jp] = c;
            }
        }
        __syncthreads();
    }

    // layernorm: 8 warps x 16 rows
    {
        int wid = tid >> 5, lane = tid & 31;
        for (int rr = 0; rr < 16; ++rr) {
            int e = wid * 16 + rr;
            int n = n0 + e;
            float v0 = Ts[e * TPAD + lane];
            float v1 = Ts[e * TPAD + lane + 32];
            float v2 = Ts[e * TPAD + lane + 64];
            float v3 = Ts[e * TPAD + lane + 96];
            float s = v0 + v1 + v2 + v3;
#pragma unroll
            for (int o = 16; o > 0; o >>= 1) s += __shfl_xor_sync(0xffffffffu, s, o);
            float mu = s * (1.0f / 128.0f);
            float d0 = v0 - mu, d1 = v1 - mu, d2 = v2 - mu, d3 = v3 - mu;
            float q = d0 * d0 + d1 * d1 + d2 * d2 + d3 * d3;
#pragma unroll
            for (int o = 16; o > 0; o >>= 1) q += __shfl_xor_sync(0xffffffffu, q, o);
            float rs = rsqrtf(q * (1.0f / 128.0f) + 1e-5f);
            if (n < NN) {
                size_t base = (size_t)n * 128;
                hout[base + lane]      = d0 * rs * lng[lane]      + lnb[lane];
                hout[base + lane + 32] = d1 * rs * lng[lane + 32] + lnb[lane + 32];
                hout[base + lane + 64] = d2 * rs * lng[lane + 64] + lnb[lane + 64];
                hout[base + lane + 96] = d3 * rs * lng[lane + 96] + lnb[lane + 96];
            }
        }
    }
}

// ---------------- launch ----------------
extern "C" void kernel_launch(void* const* d_in, const int* in_sizes, int n_in,
                              void* d_out, int out_size) {
    const float* x      = (const float*)d_in[0];
    const int*   ei     = (const int*)  d_in[1];
    const float* eattr  = (const float*)d_in[2];
    const float* enc_w1 = (const float*)d_in[3];
    const float* enc_b1 = (const float*)d_in[4];
    const float* enc_w2 = (const float*)d_in[5];
    const float* enc_b2 = (const float*)d_in[6];
    const float* msg_w1 = (const float*)d_in[7];   // [4,259,128]
    const float* msg_b1 = (const float*)d_in[8];
    const float* msg_w2 = (const float*)d_in[9];   // [4,128,128]
    const float* msg_b2 = (const float*)d_in[10];
    const float* upd_w1 = (const float*)d_in[11];  // [4,256,128]
    const float* upd_b1 = (const float*)d_in[12];
    const float* upd_w2 = (const float*)d_in[13];  // [4,128,128]
    const float* upd_b2 = (const float*)d_in[14];
    const float* ln_g   = (const float*)d_in[15];
    const float* ln_b   = (const float*)d_in[16];
    const float* dec_w1 = (const float*)d_in[17];
    const float* dec_b1 = (const float*)d_in[18];
    const float* dec_w2 = (const float*)d_in[19];
    const float* dec_b2 = (const float*)d_in[20];
    float* out = (float*)d_out;

    cudaFuncSetAttribute(k_pq,     cudaFuncAttributeMaxDynamicSharedMemorySize, SM_PQ);
    cudaFuncSetAttribute(k_edge,   cudaFuncAttributeMaxDynamicSharedMemorySize, SM_EDGE);
    cudaFuncSetAttribute(k_update, cudaFuncAttributeMaxDynamicSharedMemorySize, SM_UPD);

    k_zero_cnt<<<(NN + 255) / 256, 256>>>();
    k_count<<<(EE + 255) / 256, 256>>>(ei);
    k_inv<<<(NN + 255) / 256, 256>>>();
    k_enc<<<NN, 128>>>(x, enc_w1, enc_b1, enc_w2, enc_b2);

    for (int l = 0; l < 4; ++l) {
        int flip = l & 1;
        k_zero_agg<<<(NN * HH / 4 + 255) / 256, 256>>>();
        dim3 gpq((NN + 127) / 128, 2);
        k_pq<<<gpq, 256, SM_PQ>>>(msg_w1 + (size_t)l * 259 * 128, flip);
        k_edge<<<EE / 128, 256, SM_EDGE>>>(
            ei, eattr,
            msg_w1 + (size_t)l * 259 * 128, msg_b1 + (size_t)l * 128,
            msg_w2 + (size_t)l * 128 * 128, msg_b2 + (size_t)l * 128);
        k_update<<<(NN + 127) / 128, 256, SM_UPD>>>(
            upd_w1 + (size_t)l * 256 * 128, upd_b1 + (size_t)l * 128,
            upd_w2 + (size_t)l * 128 * 128, upd_b2 + (size_t)l * 128,
            ln_g + (size_t)l * 128, ln_b + (size_t)l * 128, flip);
    }
    k_dec<<<NN, 128>>>(dec_w1, dec_b1, dec_w2, dec_b2, out);
}

// round 4
// speedup vs baseline: 8.9762x; 2.8676x over previous
#include <cuda_runtime.h>
#include <cstdint>

#define NN 10000
#define EE 400000
#define HH 128
#define TPAD 132
#define APAD 36

typedef unsigned long long u64;

// ---------------- device scratch ----------------
__device__ float g_h  [NN * HH];
__device__ float g_hn [NN * HH];
__device__ float g_agg[NN * HH];     // Rmean (already /count)
__device__ float g_P  [NN * HH];
__device__ float g_Q  [NN * HH];
__device__ float g_inv [NN];
__device__ float g_flag[NN];
__device__ int   g_cnt[NN];
__device__ int   g_off[NN];
__device__ int   g_cur[NN];
__device__ float4 g_rec[EE];         // sorted-by-target edge records {srcbits, ea0, ea1, ea2}
__device__ float g_Wc[4][HH * HH];   // W2m @ Wb (update fusion)
__device__ float g_bc[4][HH];        // b2m @ Wb

// ---------------- packed f32x2 helpers (sm_103a) ----------------
__device__ __forceinline__ u64 pack2(float x, float y) {
    u64 r; asm("mov.b64 %0,{%1,%2};" : "=l"(r) : "f"(x), "f"(y)); return r;
}
__device__ __forceinline__ float2 unpack2(u64 v) {
    float2 r; asm("mov.b64 {%0,%1},%2;" : "=f"(r.x), "=f"(r.y) : "l"(v)); return r;
}
__device__ __forceinline__ void ffma2(u64 &c, u64 a, u64 b) {
    asm("fma.rn.f32x2 %0,%1,%2,%0;" : "+l"(c) : "l"(a), "l"(b));
}

// row-major 32-K-tile micro-kernel
__device__ __forceinline__ void mm_row(const float* __restrict__ A, int lda,
                                       int arow0, int kbase,
                                       const float* __restrict__ Bs,
                                       int tx, u64 acc[8][4]) {
#pragma unroll
    for (int kq = 0; kq < 8; ++kq) {
        int k0 = kq * 4;
        u64 bb[4][4];
#pragma unroll
        for (int kk = 0; kk < 4; ++kk) {
            const float* br = &Bs[(k0 + kk) * 128 + tx * 8];
            float4 b0 = *(const float4*)br;
            float4 b1 = *(const float4*)(br + 4);
            bb[kk][0] = pack2(b0.x, b0.y); bb[kk][1] = pack2(b0.z, b0.w);
            bb[kk][2] = pack2(b1.x, b1.y); bb[kk][3] = pack2(b1.z, b1.w);
        }
#pragma unroll
        for (int i = 0; i < 8; ++i) {
            float4 av = *(const float4*)&A[(arow0 + i) * lda + kbase + k0];
            float af[4] = { av.x, av.y, av.z, av.w };
#pragma unroll
            for (int kk = 0; kk < 4; ++kk) {
                u64 aa = pack2(af[kk], af[kk]);
#pragma unroll
                for (int jp = 0; jp < 4; ++jp) ffma2(acc[i][jp], aa, bb[kk][jp]);
            }
        }
    }
}

// ---------------- sort pipeline ----------------
__global__ void k_zero_cnt() {
    int i = blockIdx.x * blockDim.x + threadIdx.x;
    if (i < NN) g_cnt[i] = 0;
}
__global__ void k_count(const int* __restrict__ ei) {
    int e = blockIdx.x * blockDim.x + threadIdx.x;
    if (e < EE) atomicAdd(&g_cnt[ei[EE + e]], 1);
}
// single-block exclusive scan over 10000 counts; also derive inv & flag
__global__ void k_scan() {
    __shared__ int ssum[256];
    int tid = threadIdx.x;
    int base = tid * 40;
    int s = 0;
    for (int i = 0; i < 40; ++i) {
        int n = base + i;
        if (n < NN) s += g_cnt[n];
    }
    ssum[tid] = s;
    __syncthreads();
    for (int o = 1; o < 256; o <<= 1) {
        int u = (tid >= o) ? ssum[tid - o] : 0;
        int v = ssum[tid];
        __syncthreads();
        ssum[tid] = u + v;
        __syncthreads();
    }
    int run = (tid > 0) ? ssum[tid - 1] : 0;
    for (int i = 0; i < 40; ++i) {
        int n = base + i;
        if (n < NN) {
            int c = g_cnt[n];
            g_off[n] = run;
            g_cur[n] = run;
            g_inv[n]  = 1.0f / fmaxf((float)c, 1.0f);
            g_flag[n] = (c > 0) ? 1.0f : 0.0f;
            run += c;
        }
    }
}
__global__ void k_place(const int* __restrict__ ei, const float* __restrict__ ea) {
    int e = blockIdx.x * blockDim.x + threadIdx.x;
    if (e >= EE) return;
    int tgt = ei[EE + e], src = ei[e];
    int pos = atomicAdd(&g_cur[tgt], 1);
    float4 r;
    r.x = __int_as_float(src);
    r.y = ea[(size_t)e * 3];
    r.z = ea[(size_t)e * 3 + 1];
    r.w = ea[(size_t)e * 3 + 2];
    g_rec[pos] = r;
}

// ---------------- update-fusion precompute: Wc = W2m @ Wb, bc = b2m @ Wb ----------------
__global__ void k_fusew(const float* __restrict__ msg_w2, const float* __restrict__ upd_w1) {
    int l = blockIdx.y, k = blockIdx.x, c = threadIdx.x;
    __shared__ float row[128];
    row[c] = msg_w2[(size_t)l * 16384 + k * 128 + c];
    __syncthreads();
    const float* Wb = upd_w1 + (size_t)l * 32768 + 128 * 128;
    float s = 0.f;
#pragma unroll 8
    for (int j = 0; j < 128; ++j) s += row[j] * Wb[j * 128 + c];
    g_Wc[l][k * 128 + c] = s;
}
__global__ void k_fuseb(const float* __restrict__ msg_b2, const float* __restrict__ upd_w1) {
    int l = blockIdx.x, c = threadIdx.x;
    __shared__ float row[128];
    row[c] = msg_b2[l * 128 + c];
    __syncthreads();
    const float* Wb = upd_w1 + (size_t)l * 32768 + 128 * 128;
    float s = 0.f;
#pragma unroll 8
    for (int j = 0; j < 128; ++j) s += row[j] * Wb[j * 128 + c];
    g_bc[l][c] = s;
}

// ---------------- encoder stage 1: t = relu(x@w1+b1) -> g_hn ----------------
__global__ void k_enc1(const float* __restrict__ x,
                       const float* __restrict__ w1, const float* __restrict__ b1) {
    int idx = blockIdx.x * blockDim.x + threadIdx.x;
    if (idx >= NN * HH) return;
    int n = idx >> 7, j = idx & 127;
    const float* xr = x + (size_t)n * 6;
    float s = b1[j];
#pragma unroll
    for (int k = 0; k < 6; ++k) s += xr[k] * w1[k * 128 + j];
    g_hn[idx] = fmaxf(s, 0.f);
}

// ---------------- generic N x 128 x 128 GEMM: out = A@W (+bias) (opt relu) ----------------
// asel: 0 = g_h, 1 = g_hn. osel: 0 g_h, 1 g_hn, 2 g_P, 3 g_Q.
#define SM_G ((128 * APAD + 32 * 128) * 4)
__global__ __launch_bounds__(256, 2) void k_gemm128(
    int asel, const float* __restrict__ W, const float* __restrict__ bias,
    int osel, int dorelu) {
    const float* __restrict__ A = asel ? g_hn : g_h;
    float* __restrict__ outp = (osel == 0) ? g_h : (osel == 1) ? g_hn
                              : (osel == 2) ? g_P : g_Q;
    extern __shared__ float sm[];
    float* As = sm;
    float* Bs = sm + 128 * APAD;
    int tid = threadIdx.x;
    int tx = tid & 15, ty = tid >> 4;
    int n0 = blockIdx.x * 128;

    u64 acc[8][4];
#pragma unroll
    for (int i = 0; i < 8; ++i)
#pragma unroll
        for (int jp = 0; jp < 4; ++jp) acc[i][jp] = 0ull;

    for (int kt = 0; kt < 4; ++kt) {
        int kb = kt * 32;
        __syncthreads();
#pragma unroll
        for (int r = 0; r < 4; ++r) {
            int idx = r * 256 + tid;
            int e = idx >> 3, c4 = idx & 7;
            int n = n0 + e;
            float4 v = make_float4(0.f, 0.f, 0.f, 0.f);
            if (n < NN) v = *(const float4*)&A[(size_t)n * 128 + kb + c4 * 4];
            *(float4*)&As[e * APAD + c4 * 4] = v;
        }
#pragma unroll
        for (int r = 0; r < 16; ++r) {
            int idx = r * 256 + tid;
            int kk = idx >> 7, j = idx & 127;
            Bs[kk * 128 + j] = W[(size_t)(kb + kk) * 128 + j];
        }
        __syncthreads();
        mm_row(As, APAD, ty * 8, 0, Bs, tx, acc);
    }

    float bj[8];
#pragma unroll
    for (int q = 0; q < 8; ++q) bj[q] = bias ? bias[tx * 8 + q] : 0.f;
#pragma unroll
    for (int i = 0; i < 8; ++i) {
        int n = n0 + ty * 8 + i;
        if (n < NN) {
#pragma unroll
            for (int jp = 0; jp < 4; ++jp) {
                float2 c = unpack2(acc[i][jp]);
                c.x += bj[2 * jp];
                c.y += bj[2 * jp + 1];
                if (dorelu) { c.x = fmaxf(c.x, 0.f); c.y = fmaxf(c.y, 0.f); }
                *(float2*)&outp[(size_t)n * 128 + tx * 8 + 2 * jp] = c;
            }
        }
    }
}

// ---------------- segmented edge reduction: Rmean[n] = inv * sum relu(P[n]+Q[src]+ea@W1c) ----------------
// warp per node, 8 warps/block, NN/8 = 1250 blocks
__global__ void k_edge_seg(const float* __restrict__ W1) {
    int wid = threadIdx.x >> 5, lane = threadIdx.x & 31;
    int n = blockIdx.x * 8 + wid;
    if (n >= NN) return;
    int c4 = lane * 4;
    float4 P4  = *(const float4*)&g_P[(size_t)n * 128 + c4];
    float4 wc0 = *(const float4*)&W1[(size_t)256 * 128 + c4];
    float4 wc1 = *(const float4*)&W1[(size_t)257 * 128 + c4];
    float4 wc2 = *(const float4*)&W1[(size_t)258 * 128 + c4];
    int start = g_off[n], deg = g_cnt[n];
    float4 acc = make_float4(0.f, 0.f, 0.f, 0.f);
    float4 rec = (deg > 0) ? g_rec[start] : make_float4(0.f, 0.f, 0.f, 0.f);
    for (int i = 0; i < deg; ++i) {
        float4 nrec = (i + 1 < deg) ? g_rec[start + i + 1] : rec;
        int src = __float_as_int(rec.x);
        float4 q = *(const float4*)&g_Q[(size_t)src * 128 + c4];
        float vx = P4.x + q.x + rec.y * wc0.x + rec.z * wc1.x + rec.w * wc2.x;
        float vy = P4.y + q.y + rec.y * wc0.y + rec.z * wc1.y + rec.w * wc2.y;
        float vz = P4.z + q.z + rec.y * wc0.z + rec.z * wc1.z + rec.w * wc2.z;
        float vw = P4.w + q.w + rec.y * wc0.w + rec.z * wc1.w + rec.w * wc2.w;
        acc.x += fmaxf(vx, 0.f);
        acc.y += fmaxf(vy, 0.f);
        acc.z += fmaxf(vz, 0.f);
        acc.w += fmaxf(vw, 0.f);
        rec = nrec;
    }
    float iv = g_inv[n];
    *(float4*)&g_agg[(size_t)n * 128 + c4] =
        make_float4(acc.x * iv, acc.y * iv, acc.z * iv, acc.w * iv);
}

// ---------------- update MLP (fused agg-GEMM) + residual + layernorm ----------------
#define SM_UPD ((128 * APAD + 32 * 128 + 128 * TPAD) * 4)
__global__ __launch_bounds__(256, 2) void k_update(
    const float* __restrict__ W1top, const float* __restrict__ B1,
    int layer,
    const float* __restrict__ W2, const float* __restrict__ B2,
    const float* __restrict__ lng, const float* __restrict__ lnb, int flip) {
    const float* __restrict__ hin  = flip ? g_hn : g_h;
    float* __restrict__ hout       = flip ? g_h  : g_hn;
    extern __shared__ float sm[];
    float* As = sm;
    float* Bs = sm + 128 * APAD;
    float* Ts = Bs + 32 * 128;
    __shared__ float s_flag[128];
    __shared__ float s_bc[128];

    int tid = threadIdx.x;
    int tx = tid & 15, ty = tid >> 4;
    int n0 = blockIdx.x * 128;
    const float* __restrict__ Wc = g_Wc[layer];

    if (tid < 128) {
        int n = n0 + tid;
        s_flag[tid] = (n < NN) ? g_flag[n] : 0.f;
        s_bc[tid] = g_bc[layer][tid];
    }

    u64 acc[8][4];
#pragma unroll
    for (int i = 0; i < 8; ++i)
#pragma unroll
        for (int jp = 0; jp < 4; ++jp) acc[i][jp] = 0ull;

    // GEMM1: K=256 : h@Wa + Rmean@Wc
    for (int kt = 0; kt < 8; ++kt) {
        int kb = kt * 32;
        __syncthreads();
#pragma unroll
        for (int r = 0; r < 4; ++r) {
            int idx = r * 256 + tid;
            int e = idx >> 3, c4 = idx & 7;
            int n = n0 + e;
            float4 v = make_float4(0.f, 0.f, 0.f, 0.f);
            if (n < NN) {
                if (kb < 128) v = *(const float4*)&hin[(size_t)n * 128 + kb + c4 * 4];
                else          v = *(const float4*)&g_agg[(size_t)n * 128 + (kb - 128) + c4 * 4];
            }
            *(float4*)&As[e * APAD + c4 * 4] = v;
        }
#pragma unroll
        for (int r = 0; r < 16; ++r) {
            int idx = r * 256 + tid;
            int kk = idx >> 7, j = idx & 127;
            float w;
            if (kb < 128) w = W1top[(size_t)(kb + kk) * 128 + j];
            else          w = Wc[(size_t)(kb - 128 + kk) * 128 + j];
            Bs[kk * 128 + j] = w;
        }
        __syncthreads();
        mm_row(As, APAD, ty * 8, 0, Bs, tx, acc);
    }

    // epilogue1: relu(+ b1u + flag*bc) -> Ts
    {
        float bj[8], bc[8];
#pragma unroll
        for (int q = 0; q < 8; ++q) { bj[q] = B1[tx * 8 + q]; bc[q] = s_bc[tx * 8 + q]; }
        __syncthreads();
#pragma unroll
        for (int i = 0; i < 8; ++i) {
            int e = ty * 8 + i;
            float fz = s_flag[e];
#pragma unroll
            for (int jp = 0; jp < 4; ++jp) {
                float2 c = unpack2(acc[i][jp]);
                c.x = fmaxf(c.x + bj[2 * jp]     + fz * bc[2 * jp],     0.f);
                c.y = fmaxf(c.y + bj[2 * jp + 1] + fz * bc[2 * jp + 1], 0.f);
                *(float2*)&Ts[e * TPAD + tx * 8 + 2 * jp] = c;
            }
        }
        __syncthreads();
    }

    // GEMM2: K=128
    u64 acc2[8][4];
#pragma unroll
    for (int i = 0; i < 8; ++i)
#pragma unroll
        for (int jp = 0; jp < 4; ++jp) acc2[i][jp] = 0ull;

    for (int kt = 0; kt < 4; ++kt) {
        __syncthreads();
#pragma unroll
        for (int r = 0; r < 16; ++r) {
            int idx = r * 256 + tid;
            int kk = idx >> 7, j = idx & 127;
            Bs[kk * 128 + j] = W2[(size_t)(kt * 32 + kk) * 128 + j];
        }
        __syncthreads();
        mm_row(Ts, TPAD, ty * 8, kt * 32, Bs, tx, acc2);
    }

    // epilogue2: r = u + b2 + h -> Ts
    {
        float bj[8];
#pragma unroll
        for (int q = 0; q < 8; ++q) bj[q] = B2[tx * 8 + q];
        __syncthreads();
#pragma unroll
        for (int i = 0; i < 8; ++i) {
            int e = ty * 8 + i;
            int n = n0 + e;
#pragma unroll
            for (int jp = 0; jp < 4; ++jp) {
                float2 c = unpack2(acc2[i][jp]);
                float h0 = 0.f, h1 = 0.f;
                if (n < NN) {
                    float2 hv = *(const float2*)&hin[(size_t)n * 128 + tx * 8 + 2 * jp];
                    h0 = hv.x; h1 = hv.y;
                }
                c.x += bj[2 * jp] + h0;
                c.y += bj[2 * jp + 1] + h1;
                *(float2*)&Ts[e * TPAD + tx * 8 + 2 * jp] = c;
            }
        }
        __syncthreads();
    }

    // layernorm
    {
        int wid = tid >> 5, lane = tid & 31;
        for (int rr = 0; rr < 16; ++rr) {
            int e = wid * 16 + rr;
            int n = n0 + e;
            float v0 = Ts[e * TPAD + lane];
            float v1 = Ts[e * TPAD + lane + 32];
            float v2 = Ts[e * TPAD + lane + 64];
            float v3 = Ts[e * TPAD + lane + 96];
            float s = v0 + v1 + v2 + v3;
#pragma unroll
            for (int o = 16; o > 0; o >>= 1) s += __shfl_xor_sync(0xffffffffu, s, o);
            float mu = s * (1.0f / 128.0f);
            float d0 = v0 - mu, d1 = v1 - mu, d2 = v2 - mu, d3 = v3 - mu;
            float q = d0 * d0 + d1 * d1 + d2 * d2 + d3 * d3;
#pragma unroll
            for (int o = 16; o > 0; o >>= 1) q += __shfl_xor_sync(0xffffffffu, q, o);
            float rs = rsqrtf(q * (1.0f / 128.0f) + 1e-5f);
            if (n < NN) {
                size_t base = (size_t)n * 128;
                hout[base + lane]      = d0 * rs * lng[lane]      + lnb[lane];
                hout[base + lane + 32] = d1 * rs * lng[lane + 32] + lnb[lane + 32];
                hout[base + lane + 64] = d2 * rs * lng[lane + 64] + lnb[lane + 64];
                hout[base + lane + 96] = d3 * rs * lng[lane + 96] + lnb[lane + 96];
            }
        }
    }
}

// ---------------- decoder dot: out[n] = relu_t[n] . w2 + b2 ----------------
__global__ void k_dot(const float* __restrict__ w2, const float* __restrict__ b2,
                      float* __restrict__ out) {
    int wid = threadIdx.x >> 5, lane = threadIdx.x & 31;
    int n = blockIdx.x * 8 + wid;
    if (n >= NN) return;
    float4 t = *(const float4*)&g_hn[(size_t)n * 128 + lane * 4];
    float4 w = *(const float4*)&w2[lane * 4];
    float s = t.x * w.x + t.y * w.y + t.z * w.z + t.w * w.w;
#pragma unroll
    for (int o = 16; o > 0; o >>= 1) s += __shfl_xor_sync(0xffffffffu, s, o);
    if (lane == 0) out[n] = s + b2[0];
}

// ---------------- launch ----------------
extern "C" void kernel_launch(void* const* d_in, const int* in_sizes, int n_in,
                              void* d_out, int out_size) {
    const float* x      = (const float*)d_in[0];
    const int*   ei     = (const int*)  d_in[1];
    const float* eattr  = (const float*)d_in[2];
    const float* enc_w1 = (const float*)d_in[3];
    const float* enc_b1 = (const float*)d_in[4];
    const float* enc_w2 = (const float*)d_in[5];
    const float* enc_b2 = (const float*)d_in[6];
    const float* msg_w1 = (const float*)d_in[7];   // [4,259,128]
    const float* msg_b1 = (const float*)d_in[8];
    const float* msg_w2 = (const float*)d_in[9];   // [4,128,128]
    const float* msg_b2 = (const float*)d_in[10];
    const float* upd_w1 = (const float*)d_in[11];  // [4,256,128]
    const float* upd_b1 = (const float*)d_in[12];
    const float* upd_w2 = (const float*)d_in[13];
    const float* upd_b2 = (const float*)d_in[14];
    const float* ln_g   = (const float*)d_in[15];
    const float* ln_b   = (const float*)d_in[16];
    const float* dec_w1 = (const float*)d_in[17];
    const float* dec_b1 = (const float*)d_in[18];
    const float* dec_w2 = (const float*)d_in[19];
    const float* dec_b2 = (const float*)d_in[20];
    float* out = (float*)d_out;

    cudaFuncSetAttribute(k_gemm128, cudaFuncAttributeMaxDynamicSharedMemorySize, SM_G);
    cudaFuncSetAttribute(k_update,  cudaFuncAttributeMaxDynamicSharedMemorySize, SM_UPD);

    // sort edges by target (counting sort) + degree stats
    k_zero_cnt<<<(NN + 255) / 256, 256>>>();
    k_count<<<(EE + 255) / 256, 256>>>(ei);
    k_scan<<<1, 256>>>();
    k_place<<<(EE + 255) / 256, 256>>>(ei, eattr);

    // fusion precompute (layer-independent of h)
    k_fusew<<<dim3(128, 4), 128>>>(msg_w2, upd_w1);
    k_fuseb<<<4, 128>>>(msg_b2, upd_w1);

    // encoder
    k_enc1<<<(NN * HH + 255) / 256, 256>>>(x, enc_w1, enc_b1);
    k_gemm128<<<(NN + 127) / 128, 256, SM_G>>>(1, enc_w2, enc_b2, 0, 0);  // g_hn -> g_h

    for (int l = 0; l < 4; ++l) {
        int flip = l & 1;                     // hin = flip ? g_hn : g_h
        const float* W1l = msg_w1 + (size_t)l * 259 * 128;
        // P = h@Wa + b1m ; Q = h@Wb
        k_gemm128<<<(NN + 127) / 128, 256, SM_G>>>(flip, W1l, msg_b1 + (size_t)l * 128, 2, 0);
        k_gemm128<<<(NN + 127) / 128, 256, SM_G>>>(flip, W1l + 128 * 128, nullptr, 3, 0);
        k_edge_seg<<<NN / 8, 256>>>(W1l);
        k_update<<<(NN + 127) / 128, 256, SM_UPD>>>(
            upd_w1 + (size_t)l * 256 * 128, upd_b1 + (size_t)l * 128, l,
            upd_w2 + (size_t)l * 128 * 128, upd_b2 + (size_t)l * 128,
            ln_g + (size_t)l * 128, ln_b + (size_t)l * 128, flip);
    }

    // decoder: t = relu(h@dec_w1 + b1) -> g_hn ; out = t.dec_w2 + b2
    k_gemm128<<<(NN + 127) / 128, 256, SM_G>>>(0, dec_w1, dec_b1, 1, 1);
    k_dot<<<NN / 8, 256>>>(dec_w2, dec_b2, out);
}